// round 10
// baseline (speedup 1.0000x reference)
#include <cuda_runtime.h>

#define BB 16
#define CC 1024
#define NLOC 3136            // 16*14*14
#define N4 784               // NLOC/4
#define CSPLIT 8
#define CCHUNK 128           // CC/CSPLIT
#define MARGIN 0.2f
#define INV_TEMP 1000.0f
#define SCALE 100000.0f

// Reduced dot accumulators. Zero at module load; softmax kernel re-zeroes
// them after consuming, so every replay starts clean.
__device__ float4 g_pd[BB * N4];
__device__ float4 g_nd[BB * N4];

// ---------------------------------------------------------------------------
// Kernel 1: fused batched matvec, C split 8-ways, 2x float4 per thread (ILP).
// Partials folded via atomicAdd (REDG) into g_pd/g_nd (L2-resident).
// grid = (4, 8, 16) = 512 blocks, block = 128.
// ---------------------------------------------------------------------------
__global__ void __launch_bounds__(128)
dot_kernel(const float* __restrict__ ft,
           const float* __restrict__ pos,
           const float* __restrict__ neg,
           float* __restrict__ out, int out_size)
{
    __shared__ float s_pos[CCHUNK];
    __shared__ float s_neg[CCHUNK];
    const int b  = blockIdx.z;
    const int cs = blockIdx.y;
    const int c0 = cs * CCHUNK;

    if (blockIdx.x == 0 && blockIdx.y == 0 && blockIdx.z == 0 &&
        threadIdx.x == 0 && out_size > BB * NLOC)
        out[BB * NLOC] = 0.0f;

    s_pos[threadIdx.x] = pos[b * CC + c0 + threadIdx.x];
    s_neg[threadIdx.x] = neg[b * CC + c0 + threadIdx.x];
    __syncthreads();

    const int na = blockIdx.x * 256 + threadIdx.x;   // stream A
    const int nb = na + 128;                         // stream B
    const bool va = na < N4;
    const bool vb = nb < N4;

    const float4* baseA = (const float4*)(ft + (size_t)b * CC * NLOC
                                             + (size_t)c0 * NLOC) + na;
    const float4* baseB = baseA + 128;

    float4 pdA = {0.f,0.f,0.f,0.f}, ndA = {0.f,0.f,0.f,0.f};
    float4 pdB = {0.f,0.f,0.f,0.f}, ndB = {0.f,0.f,0.f,0.f};

#pragma unroll 8
    for (int c = 0; c < CCHUNK; ++c) {
        float sp = s_pos[c], sn = s_neg[c];
        if (va) {
            float4 v = __ldg(baseA + (size_t)c * N4);
            pdA.x = fmaf(v.x, sp, pdA.x);  pdA.y = fmaf(v.y, sp, pdA.y);
            pdA.z = fmaf(v.z, sp, pdA.z);  pdA.w = fmaf(v.w, sp, pdA.w);
            ndA.x = fmaf(v.x, sn, ndA.x);  ndA.y = fmaf(v.y, sn, ndA.y);
            ndA.z = fmaf(v.z, sn, ndA.z);  ndA.w = fmaf(v.w, sn, ndA.w);
        }
        if (vb) {
            float4 v = __ldg(baseB + (size_t)c * N4);
            pdB.x = fmaf(v.x, sp, pdB.x);  pdB.y = fmaf(v.y, sp, pdB.y);
            pdB.z = fmaf(v.z, sp, pdB.z);  pdB.w = fmaf(v.w, sp, pdB.w);
            ndB.x = fmaf(v.x, sn, ndB.x);  ndB.y = fmaf(v.y, sn, ndB.y);
            ndB.z = fmaf(v.z, sn, ndB.z);  ndB.w = fmaf(v.w, sn, ndB.w);
        }
    }

    if (va) {
        float* dp = (float*)&g_pd[b * N4 + na];
        float* dn = (float*)&g_nd[b * N4 + na];
        atomicAdd(dp + 0, pdA.x);  atomicAdd(dp + 1, pdA.y);
        atomicAdd(dp + 2, pdA.z);  atomicAdd(dp + 3, pdA.w);
        atomicAdd(dn + 0, ndA.x);  atomicAdd(dn + 1, ndA.y);
        atomicAdd(dn + 2, ndA.z);  atomicAdd(dn + 3, ndA.w);
    }
    if (vb) {
        float* dp = (float*)&g_pd[b * N4 + nb];
        float* dn = (float*)&g_nd[b * N4 + nb];
        atomicAdd(dp + 0, pdB.x);  atomicAdd(dp + 1, pdB.y);
        atomicAdd(dp + 2, pdB.z);  atomicAdd(dp + 3, pdB.w);
        atomicAdd(dn + 0, ndB.x);  atomicAdd(dn + 1, ndB.y);
        atomicAdd(dn + 2, ndB.z);  atomicAdd(dn + 3, ndB.w);
    }
}

// ---------------------------------------------------------------------------
// Kernel 2: per-batch softmax + margin loss; loss atomicAdd into out[B*N].
// grid = BB, block = 1024, row in registers (tid < 784 active).
// Zeroes g_pd/g_nd after reading so the next replay starts clean.
// ---------------------------------------------------------------------------
__global__ void __launch_bounds__(1024)
softmax_loss_kernel(float* __restrict__ out, int out_size)
{
    const int b   = blockIdx.x;
    const int tid = threadIdx.x;
    __shared__ float red[32];
    const bool act = tid < N4;

    float4 pd = {-1e30f, -1e30f, -1e30f, -1e30f};
    float4 nd = {0.f, 0.f, 0.f, 0.f};
    const float4 z4 = {0.f, 0.f, 0.f, 0.f};
    if (act) {
        pd = g_pd[b * N4 + tid];
        nd = g_nd[b * N4 + tid];
        g_pd[b * N4 + tid] = z4;   // reset for next replay
        g_nd[b * N4 + tid] = z4;
    }

    // ---- block max ----
    float m = fmaxf(fmaxf(pd.x, pd.y), fmaxf(pd.z, pd.w));
#pragma unroll
    for (int o = 16; o > 0; o >>= 1)
        m = fmaxf(m, __shfl_xor_sync(0xffffffffu, m, o));
    if ((tid & 31) == 0) red[tid >> 5] = m;
    __syncthreads();
    if (tid < 32) {
        float v = red[tid];
#pragma unroll
        for (int o = 16; o > 0; o >>= 1)
            v = fmaxf(v, __shfl_xor_sync(0xffffffffu, v, o));
        if (tid == 0) red[0] = v;
    }
    __syncthreads();
    const float mx = red[0];
    __syncthreads();

    // ---- exp + block sum ----
    float4 e = {0.f, 0.f, 0.f, 0.f};
    if (act) {
        e.x = expf((pd.x - mx) * INV_TEMP);
        e.y = expf((pd.y - mx) * INV_TEMP);
        e.z = expf((pd.z - mx) * INV_TEMP);
        e.w = expf((pd.w - mx) * INV_TEMP);
    }
    float s = e.x + e.y + e.z + e.w;
#pragma unroll
    for (int o = 16; o > 0; o >>= 1)
        s += __shfl_xor_sync(0xffffffffu, s, o);
    if ((tid & 31) == 0) red[tid >> 5] = s;
    __syncthreads();
    if (tid < 32) {
        float v = red[tid];
#pragma unroll
        for (int o = 16; o > 0; o >>= 1)
            v += __shfl_xor_sync(0xffffffffu, v, o);
        if (tid == 0) red[0] = v;
    }
    __syncthreads();
    const float invZ = 1.0f / red[0];
    __syncthreads();

    // ---- attn write + loss partial ----
    float l = 0.0f;
    if (act) {
        float4 a;
        a.x = e.x * invZ;  a.y = e.y * invZ;
        a.z = e.z * invZ;  a.w = e.w * invZ;
        ((float4*)(out + b * NLOC))[tid] = a;
        l = fmaf(fmaxf(MARGIN + (nd.x - pd.x) * SCALE, 0.0f), a.x, l);
        l = fmaf(fmaxf(MARGIN + (nd.y - pd.y) * SCALE, 0.0f), a.y, l);
        l = fmaf(fmaxf(MARGIN + (nd.z - pd.z) * SCALE, 0.0f), a.z, l);
        l = fmaf(fmaxf(MARGIN + (nd.w - pd.w) * SCALE, 0.0f), a.w, l);
    }
#pragma unroll
    for (int o = 16; o > 0; o >>= 1)
        l += __shfl_xor_sync(0xffffffffu, l, o);
    if ((tid & 31) == 0) red[tid >> 5] = l;
    __syncthreads();
    if (tid < 32) {
        float v = red[tid];
#pragma unroll
        for (int o = 16; o > 0; o >>= 1)
            v += __shfl_xor_sync(0xffffffffu, v, o);
        if (tid == 0 && out_size > BB * NLOC)
            atomicAdd(out + BB * NLOC, v * (1.0f / (float)BB));
    }
}

extern "C" void kernel_launch(void* const* d_in, const int* in_sizes, int n_in,
                              void* d_out, int out_size)
{
    const float* ft  = (const float*)d_in[0];
    const float* pos = (const float*)d_in[1];
    const float* neg = (const float*)d_in[2];
    float* out = (float*)d_out;

    dim3 grid1(4, CSPLIT, BB);
    dot_kernel<<<grid1, 128>>>(ft, pos, neg, out, out_size);

    softmax_loss_kernel<<<BB, 1024>>>(out, out_size);
}

// round 11
// speedup vs baseline: 1.9383x; 1.9383x over previous
#include <cuda_runtime.h>

#define BB 16
#define CC 1024
#define NLOC 3136            // 16*14*14
#define N4 784               // NLOC/4
#define CSPLIT 8
#define CCHUNK 128           // CC/CSPLIT
#define MARGIN 0.2f
#define INV_TEMP 1000.0f
#define SCALE 100000.0f

// Reduced dot accumulators. Zero at module load; softmax kernel re-zeroes
// them after consuming, so every replay starts clean.
__device__ float4 g_pd[BB * N4];
__device__ float4 g_nd[BB * N4];

// ---------------------------------------------------------------------------
// Kernel 1 (R8-validated, 896 blocks): fused batched matvec, C split 8-ways,
// float4 loads, partials folded via atomicAdd (REDG) into g_pd/g_nd.
// ---------------------------------------------------------------------------
__global__ void __launch_bounds__(128)
dot_kernel(const float* __restrict__ ft,
           const float* __restrict__ pos,
           const float* __restrict__ neg,
           float* __restrict__ out, int out_size)
{
    __shared__ float s_pos[CCHUNK];
    __shared__ float s_neg[CCHUNK];
    const int b  = blockIdx.z;
    const int cs = blockIdx.y;
    const int c0 = cs * CCHUNK;

    if (blockIdx.x == 0 && blockIdx.y == 0 && blockIdx.z == 0 &&
        threadIdx.x == 0 && out_size > BB * NLOC)
        out[BB * NLOC] = 0.0f;

    s_pos[threadIdx.x] = pos[b * CC + c0 + threadIdx.x];
    s_neg[threadIdx.x] = neg[b * CC + c0 + threadIdx.x];
    __syncthreads();

    const int n4 = blockIdx.x * 128 + threadIdx.x;
    if (n4 >= N4) return;

    const float4* base = (const float4*)(ft + (size_t)b * CC * NLOC
                                            + (size_t)c0 * NLOC) + n4;
    float4 pd = {0.f, 0.f, 0.f, 0.f};
    float4 nd = {0.f, 0.f, 0.f, 0.f};

#pragma unroll 8
    for (int c = 0; c < CCHUNK; ++c) {
        float4 v = __ldg(base + (size_t)c * N4);
        float sp = s_pos[c], sn = s_neg[c];
        pd.x = fmaf(v.x, sp, pd.x);  pd.y = fmaf(v.y, sp, pd.y);
        pd.z = fmaf(v.z, sp, pd.z);  pd.w = fmaf(v.w, sp, pd.w);
        nd.x = fmaf(v.x, sn, nd.x);  nd.y = fmaf(v.y, sn, nd.y);
        nd.z = fmaf(v.z, sn, nd.z);  nd.w = fmaf(v.w, sn, nd.w);
    }

    float* dp = (float*)&g_pd[b * N4 + n4];
    float* dn = (float*)&g_nd[b * N4 + n4];
    atomicAdd(dp + 0, pd.x);  atomicAdd(dp + 1, pd.y);
    atomicAdd(dp + 2, pd.z);  atomicAdd(dp + 3, pd.w);
    atomicAdd(dn + 0, nd.x);  atomicAdd(dn + 1, nd.y);
    atomicAdd(dn + 2, nd.z);  atomicAdd(dn + 3, nd.w);
}

// ---------------------------------------------------------------------------
// Kernel 2: per-batch softmax + margin loss (latency-trimmed).
// grid = BB, block = 1024, row in registers (tid < 784 active).
// __expf (MUFU) + merged Z/loss reduction: 2 reduction rounds instead of 3.
// Zeroes g_pd/g_nd after reading so the next replay starts clean.
// ---------------------------------------------------------------------------
__global__ void __launch_bounds__(1024)
softmax_loss_kernel(float* __restrict__ out, int out_size)
{
    const int b   = blockIdx.x;
    const int tid = threadIdx.x;
    __shared__ float red[32];
    __shared__ float red2[32];
    const bool act = tid < N4;

    float4 pd = {-1e30f, -1e30f, -1e30f, -1e30f};
    float4 nd = {0.f, 0.f, 0.f, 0.f};
    const float4 z4 = {0.f, 0.f, 0.f, 0.f};
    if (act) {
        pd = g_pd[b * N4 + tid];
        nd = g_nd[b * N4 + tid];
        g_pd[b * N4 + tid] = z4;   // reset for next replay
        g_nd[b * N4 + tid] = z4;
    }

    // ---- round 1: block max ----
    float m = fmaxf(fmaxf(pd.x, pd.y), fmaxf(pd.z, pd.w));
#pragma unroll
    for (int o = 16; o > 0; o >>= 1)
        m = fmaxf(m, __shfl_xor_sync(0xffffffffu, m, o));
    if ((tid & 31) == 0) red[tid >> 5] = m;
    __syncthreads();
    if (tid < 32) {
        float v = red[tid];
#pragma unroll
        for (int o = 16; o > 0; o >>= 1)
            v = fmaxf(v, __shfl_xor_sync(0xffffffffu, v, o));
        if (tid == 0) red[0] = v;
    }
    __syncthreads();
    const float mx = red[0];
    __syncthreads();

    // ---- exp (MUFU) + margin terms; merged Z / loss reduction ----
    float4 e = {0.f, 0.f, 0.f, 0.f};
    float s = 0.0f, le = 0.0f;
    if (act) {
        e.x = __expf((pd.x - mx) * INV_TEMP);
        e.y = __expf((pd.y - mx) * INV_TEMP);
        e.z = __expf((pd.z - mx) * INV_TEMP);
        e.w = __expf((pd.w - mx) * INV_TEMP);
        s = e.x + e.y + e.z + e.w;
        le = fmaf(fmaxf(MARGIN + (nd.x - pd.x) * SCALE, 0.0f), e.x, le);
        le = fmaf(fmaxf(MARGIN + (nd.y - pd.y) * SCALE, 0.0f), e.y, le);
        le = fmaf(fmaxf(MARGIN + (nd.z - pd.z) * SCALE, 0.0f), e.z, le);
        le = fmaf(fmaxf(MARGIN + (nd.w - pd.w) * SCALE, 0.0f), e.w, le);
    }
#pragma unroll
    for (int o = 16; o > 0; o >>= 1) {
        s  += __shfl_xor_sync(0xffffffffu, s, o);
        le += __shfl_xor_sync(0xffffffffu, le, o);
    }
    if ((tid & 31) == 0) { red[tid >> 5] = s;  red2[tid >> 5] = le; }
    __syncthreads();
    if (tid < 32) {
        float v = red[tid], w = red2[tid];
#pragma unroll
        for (int o = 16; o > 0; o >>= 1) {
            v += __shfl_xor_sync(0xffffffffu, v, o);
            w += __shfl_xor_sync(0xffffffffu, w, o);
        }
        if (tid == 0) { red[0] = v; red2[0] = w; }
    }
    __syncthreads();
    const float invZ = 1.0f / red[0];

    // ---- attn write; thread 0 posts the per-batch loss ----
    if (act) {
        float4 a;
        a.x = e.x * invZ;  a.y = e.y * invZ;
        a.z = e.z * invZ;  a.w = e.w * invZ;
        ((float4*)(out + b * NLOC))[tid] = a;
    }
    if (tid == 0 && out_size > BB * NLOC)
        atomicAdd(out + BB * NLOC, red2[0] * invZ * (1.0f / (float)BB));
}

extern "C" void kernel_launch(void* const* d_in, const int* in_sizes, int n_in,
                              void* d_out, int out_size)
{
    const float* ft  = (const float*)d_in[0];
    const float* pos = (const float*)d_in[1];
    const float* neg = (const float*)d_in[2];
    float* out = (float*)d_out;

    dim3 grid1(7, CSPLIT, BB);
    dot_kernel<<<grid1, 128>>>(ft, pos, neg, out, out_size);

    softmax_loss_kernel<<<BB, 1024>>>(out, out_size);
}

// round 12
// speedup vs baseline: 1.9502x; 1.0061x over previous
#include <cuda_runtime.h>

#define BB 16
#define CC 1024
#define NLOC 3136            // 16*14*14
#define N4 784               // NLOC/4
#define CSPLIT 8
#define CCHUNK 128           // CC/CSPLIT
#define MARGIN 0.2f
#define INV_TEMP 1000.0f
#define SCALE 100000.0f

// Reduced dot accumulators. Zero at module load; softmax kernel re-zeroes
// them after consuming, so every replay starts clean.
__device__ float4 g_pd[BB * N4];
__device__ float4 g_nd[BB * N4];

// ---------------------------------------------------------------------------
// Kernel 1 (R8-validated): fused batched matvec, C split 8-ways, float4
// loads, partials folded via atomicAdd (REDG) into g_pd/g_nd.
// Each block triggers programmatic launch completion after posting results.
// grid = (7, 8, 16) = 896 blocks, block = 128.
// ---------------------------------------------------------------------------
__global__ void __launch_bounds__(128)
dot_kernel(const float* __restrict__ ft,
           const float* __restrict__ pos,
           const float* __restrict__ neg,
           float* __restrict__ out, int out_size)
{
    __shared__ float s_pos[CCHUNK];
    __shared__ float s_neg[CCHUNK];
    const int b  = blockIdx.z;
    const int cs = blockIdx.y;
    const int c0 = cs * CCHUNK;

    if (blockIdx.x == 0 && blockIdx.y == 0 && blockIdx.z == 0 &&
        threadIdx.x == 0 && out_size > BB * NLOC)
        out[BB * NLOC] = 0.0f;

    s_pos[threadIdx.x] = pos[b * CC + c0 + threadIdx.x];
    s_neg[threadIdx.x] = neg[b * CC + c0 + threadIdx.x];
    __syncthreads();

    const int n4 = blockIdx.x * 128 + threadIdx.x;
    if (n4 < N4) {
        const float4* base = (const float4*)(ft + (size_t)b * CC * NLOC
                                                + (size_t)c0 * NLOC) + n4;
        float4 pd = {0.f, 0.f, 0.f, 0.f};
        float4 nd = {0.f, 0.f, 0.f, 0.f};

#pragma unroll 8
        for (int c = 0; c < CCHUNK; ++c) {
            float4 v = __ldg(base + (size_t)c * N4);
            float sp = s_pos[c], sn = s_neg[c];
            pd.x = fmaf(v.x, sp, pd.x);  pd.y = fmaf(v.y, sp, pd.y);
            pd.z = fmaf(v.z, sp, pd.z);  pd.w = fmaf(v.w, sp, pd.w);
            nd.x = fmaf(v.x, sn, nd.x);  nd.y = fmaf(v.y, sn, nd.y);
            nd.z = fmaf(v.z, sn, nd.z);  nd.w = fmaf(v.w, sn, nd.w);
        }

        float* dp = (float*)&g_pd[b * N4 + n4];
        float* dn = (float*)&g_nd[b * N4 + n4];
        atomicAdd(dp + 0, pd.x);  atomicAdd(dp + 1, pd.y);
        atomicAdd(dp + 2, pd.z);  atomicAdd(dp + 3, pd.w);
        atomicAdd(dn + 0, nd.x);  atomicAdd(dn + 1, nd.y);
        atomicAdd(dn + 2, nd.z);  atomicAdd(dn + 3, nd.w);
    }

    // Allow the dependent softmax grid to begin launching.
    cudaTriggerProgrammaticLaunchCompletion();
}

// ---------------------------------------------------------------------------
// Kernel 2 (R8-validated + PDL): per-batch softmax + margin loss.
// Launched with programmatic stream serialization: blocks spin up during the
// dot grid's drain, then cudaGridDependencySynchronize() guarantees all of
// kernel 1's memory (REDG results, out-slot zero) is visible.
// grid = BB, block = 1024, row in registers (tid < 784 active).
// ---------------------------------------------------------------------------
__global__ void __launch_bounds__(1024)
softmax_loss_kernel(float* __restrict__ out, int out_size)
{
    cudaGridDependencySynchronize();

    const int b   = blockIdx.x;
    const int tid = threadIdx.x;
    __shared__ float red[32];
    const bool act = tid < N4;

    float4 pd = {-1e30f, -1e30f, -1e30f, -1e30f};
    float4 nd = {0.f, 0.f, 0.f, 0.f};
    const float4 z4 = {0.f, 0.f, 0.f, 0.f};
    if (act) {
        pd = g_pd[b * N4 + tid];
        nd = g_nd[b * N4 + tid];
        g_pd[b * N4 + tid] = z4;   // reset for next replay
        g_nd[b * N4 + tid] = z4;
    }

    // ---- block max ----
    float m = fmaxf(fmaxf(pd.x, pd.y), fmaxf(pd.z, pd.w));
#pragma unroll
    for (int o = 16; o > 0; o >>= 1)
        m = fmaxf(m, __shfl_xor_sync(0xffffffffu, m, o));
    if ((tid & 31) == 0) red[tid >> 5] = m;
    __syncthreads();
    if (tid < 32) {
        float v = red[tid];
#pragma unroll
        for (int o = 16; o > 0; o >>= 1)
            v = fmaxf(v, __shfl_xor_sync(0xffffffffu, v, o));
        if (tid == 0) red[0] = v;
    }
    __syncthreads();
    const float mx = red[0];
    __syncthreads();

    // ---- exp + block sum ----
    float4 e = {0.f, 0.f, 0.f, 0.f};
    if (act) {
        e.x = expf((pd.x - mx) * INV_TEMP);
        e.y = expf((pd.y - mx) * INV_TEMP);
        e.z = expf((pd.z - mx) * INV_TEMP);
        e.w = expf((pd.w - mx) * INV_TEMP);
    }
    float s = e.x + e.y + e.z + e.w;
#pragma unroll
    for (int o = 16; o > 0; o >>= 1)
        s += __shfl_xor_sync(0xffffffffu, s, o);
    if ((tid & 31) == 0) red[tid >> 5] = s;
    __syncthreads();
    if (tid < 32) {
        float v = red[tid];
#pragma unroll
        for (int o = 16; o > 0; o >>= 1)
            v += __shfl_xor_sync(0xffffffffu, v, o);
        if (tid == 0) red[0] = v;
    }
    __syncthreads();
    const float invZ = 1.0f / red[0];
    __syncthreads();

    // ---- attn write + loss partial ----
    float l = 0.0f;
    if (act) {
        float4 a;
        a.x = e.x * invZ;  a.y = e.y * invZ;
        a.z = e.z * invZ;  a.w = e.w * invZ;
        ((float4*)(out + b * NLOC))[tid] = a;
        l = fmaf(fmaxf(MARGIN + (nd.x - pd.x) * SCALE, 0.0f), a.x, l);
        l = fmaf(fmaxf(MARGIN + (nd.y - pd.y) * SCALE, 0.0f), a.y, l);
        l = fmaf(fmaxf(MARGIN + (nd.z - pd.z) * SCALE, 0.0f), a.z, l);
        l = fmaf(fmaxf(MARGIN + (nd.w - pd.w) * SCALE, 0.0f), a.w, l);
    }
#pragma unroll
    for (int o = 16; o > 0; o >>= 1)
        l += __shfl_xor_sync(0xffffffffu, l, o);
    if ((tid & 31) == 0) red[tid >> 5] = l;
    __syncthreads();
    if (tid < 32) {
        float v = red[tid];
#pragma unroll
        for (int o = 16; o > 0; o >>= 1)
            v += __shfl_xor_sync(0xffffffffu, v, o);
        if (tid == 0 && out_size > BB * NLOC)
            atomicAdd(out + BB * NLOC, v * (1.0f / (float)BB));
    }
}

extern "C" void kernel_launch(void* const* d_in, const int* in_sizes, int n_in,
                              void* d_out, int out_size)
{
    const float* ft  = (const float*)d_in[0];
    const float* pos = (const float*)d_in[1];
    const float* neg = (const float*)d_in[2];
    float* out = (float*)d_out;

    dim3 grid1(7, CSPLIT, BB);
    dot_kernel<<<grid1, 128>>>(ft, pos, neg, out, out_size);

    // Dependent launch with programmatic stream serialization (PDL):
    // softmax blocks launch during the dot grid's drain.
    cudaLaunchConfig_t cfg = {};
    cfg.gridDim  = dim3(BB, 1, 1);
    cfg.blockDim = dim3(1024, 1, 1);
    cfg.dynamicSmemBytes = 0;
    cfg.stream = 0;
    cudaLaunchAttribute attrs[1];
    attrs[0].id = cudaLaunchAttributeProgrammaticStreamSerialization;
    attrs[0].val.programmaticStreamSerializationAllowed = 1;
    cfg.attrs = attrs;
    cfg.numAttrs = 1;
    cudaLaunchKernelEx(&cfg, softmax_loss_kernel, out, out_size);
}